// round 7
// baseline (speedup 1.0000x reference)
#include <cuda_runtime.h>
#include <math_constants.h>

#define B_      64
#define C_      256
#define HW_     4096            // floats per plane = 1024 float4
#define NPLANE  16384
#define NCL     8

#define GRID_   888             // 6 blocks/SM * 148 SMs — all resident
#define TPB_    256
#define NWARP_  (GRID_ * 8)     // 7104 warps

// ---------------- scratch (static __device__, no allocation) ----------------
__device__ float g_sum[NPLANE];
__device__ float g_min[NPLANE];
__device__ float g_max[NPLANE];
__device__ float g_scale[NPLANE];
__device__ float g_smin[B_];
__device__ float g_smax[B_];

// grid barrier: cnt reset by last arriver; flag monotonic across replays
__device__ unsigned g_cnt[2];
__device__ unsigned g_flag[2];

__device__ __forceinline__ void grid_sync(int k) {
    __syncthreads();
    if (threadIdx.x == 0) {
        __threadfence();
        unsigned f = *((volatile unsigned*)&g_flag[k]);
        unsigned old = atomicAdd(&g_cnt[k], 1u);
        if (old == GRID_ - 1u) {
            g_cnt[k] = 0u;
            __threadfence();
            atomicAdd(&g_flag[k], 1u);   // release
        } else {
            while (*((volatile unsigned*)&g_flag[k]) == f) { }
        }
        __threadfence();
    }
    __syncthreads();
}

__global__ __launch_bounds__(TPB_, 6) void fused_pcq(
    const float* __restrict__ x,
    const float* __restrict__ w1, const float* __restrict__ b1,
    const float* __restrict__ w2, const float* __restrict__ b2,
    const float* __restrict__ act_range,
    const int*   __restrict__ cluster,
    float* __restrict__ out)
{
    const int t    = threadIdx.x;
    const int warp = t >> 5;
    const int lane = t & 31;
    const int gw   = blockIdx.x * 8 + warp;   // 0..NWARP_-1

    // ================= Phase 1: per-plane sum / min / max ===================
    for (int plane = gw; plane < NPLANE; plane += NWARP_) {
        const float4* xp = reinterpret_cast<const float4*>(x + (size_t)plane * HW_);

        float s = 0.f, mn = CUDART_INF_F, mx = -CUDART_INF_F;
#pragma unroll 4
        for (int i = 0; i < 32; ++i) {       // 32 f4/lane * 32 lanes = 1024 f4
            float4 v = xp[lane + 32 * i];
            s += (v.x + v.y) + (v.z + v.w);
            mn = fminf(mn, fminf(fminf(v.x, v.y), fminf(v.z, v.w)));
            mx = fmaxf(mx, fmaxf(fmaxf(v.x, v.y), fmaxf(v.z, v.w)));
        }
#pragma unroll
        for (int o = 16; o; o >>= 1) {
            s  += __shfl_xor_sync(0xffffffffu, s, o);
            mn  = fminf(mn, __shfl_xor_sync(0xffffffffu, mn, o));
            mx  = fmaxf(mx, __shfl_xor_sync(0xffffffffu, mx, o));
        }
        if (lane == 0) {
            g_sum[plane] = s;
            g_min[plane] = mn;
            g_max[plane] = mx;
        }
    }

    grid_sync(0);

    // ================= Phase 2: SE MLP (blocks 0..63, one sample each) ======
    if (blockIdx.x < B_) {
        const int b = blockIdx.x;
        __shared__ float pooled[C_];
        __shared__ float hbuf[64];

        pooled[t] = g_sum[b * C_ + t] * (1.0f / 4096.0f);
        __syncthreads();

        if (t < 64) {
            float acc = b1[t];
            const float* w1r = w1 + t * C_;
#pragma unroll 8
            for (int c = 0; c < C_; ++c) acc += pooled[c] * w1r[c];
            hbuf[t] = fmaxf(acc, 0.0f);
        }
        __syncthreads();

        float v = b2[t];
        const float* w2r = w2 + t * 64;
#pragma unroll 8
        for (int s = 0; s < 64; ++s) v += hbuf[s] * w2r[s];
        float sc = fminf(fmaxf(v * (1.0f / 6.0f) + 0.5f, 0.0f), 1.0f);
        g_scale[b * C_ + t] = sc;

        float pmn = sc * g_min[b * C_ + t];   // scale >= 0
        float pmx = sc * g_max[b * C_ + t];
#pragma unroll
        for (int o = 16; o; o >>= 1) {
            pmn = fminf(pmn, __shfl_xor_sync(0xffffffffu, pmn, o));
            pmx = fmaxf(pmx, __shfl_xor_sync(0xffffffffu, pmx, o));
        }
        __shared__ float sh_mn[8], sh_mx[8];
        if (lane == 0) { sh_mn[warp] = pmn; sh_mx[warp] = pmx; }
        __syncthreads();
        if (t == 0) {
            float tmn = CUDART_INF_F, tmx = -CUDART_INF_F;
#pragma unroll
            for (int w = 0; w < 8; ++w) {
                tmn = fminf(tmn, sh_mn[w]);
                tmx = fmaxf(tmx, sh_mx[w]);
            }
            g_smin[b] = tmn;
            g_smax[b] = tmx;
        }
    }

    grid_sync(1);

    // ================= Phase 3: cluster (s,z) + streaming fake-quant ========
    __shared__ float cs_s[NCL], cs_z[NCL];
    __shared__ float s_ss[B_], s_zz[B_], s_inv[B_];

    if (t < NCL) {
        float cmin = CUDART_INF_F, cmax = -CUDART_INF_F;
        for (int b = 0; b < B_; ++b) {
            if (cluster[b] == t) {
                cmin = fminf(cmin, g_smin[b]);
                cmax = fmaxf(cmax, g_smax[b]);
            }
        }
        const float SMOOTH = 0.995f, ONE_M = 0.005f;
        float nmin = act_range[2 * t]     * SMOOTH + cmin * ONE_M;
        float nmax = act_range[2 * t + 1] * SMOOTH + cmax * ONE_M;
        float s = (nmax - nmin) * (1.0f / 255.0f);
        cs_s[t] = s;
        cs_z[t] = -rintf(nmin / s);
    }
    __syncthreads();
    if (t < B_) {
        int k = cluster[t];
        s_ss[t]  = cs_s[k];
        s_zz[t]  = cs_z[k];
        s_inv[t] = 1.0f / cs_s[k];
    }
    __syncthreads();

    // reverse order: this warp's most recently read planes are L2-hot
    const int pstart = gw + NWARP_ * ((NPLANE - 1 - gw) / NWARP_);
    for (int plane = pstart; plane >= 0; plane -= NWARP_) {
        const int b = plane >> 8;
        const float sc  = g_scale[plane];
        const float ssv = s_ss[b];
        const float zzv = s_zz[b];
        const float inv = s_inv[b];

        const float4* xp = reinterpret_cast<const float4*>(x   + (size_t)plane * HW_);
        float4*       op = reinterpret_cast<float4*>      (out + (size_t)plane * HW_);

#pragma unroll 2
        for (int i = 0; i < 32; ++i) {
            float4 v = xp[lane + 32 * i];
            float4 r;
            {
                float o = sc * v.x;
                float q = fminf(fmaxf(rintf(fmaf(o, inv, zzv)), 0.0f), 255.0f);
                r.x = (q - zzv) * ssv;
            }
            {
                float o = sc * v.y;
                float q = fminf(fmaxf(rintf(fmaf(o, inv, zzv)), 0.0f), 255.0f);
                r.y = (q - zzv) * ssv;
            }
            {
                float o = sc * v.z;
                float q = fminf(fmaxf(rintf(fmaf(o, inv, zzv)), 0.0f), 255.0f);
                r.z = (q - zzv) * ssv;
            }
            {
                float o = sc * v.w;
                float q = fminf(fmaxf(rintf(fmaf(o, inv, zzv)), 0.0f), 255.0f);
                r.w = (q - zzv) * ssv;
            }
            __stcs(&op[lane + 32 * i], r);
        }
    }
}

// ---------------- launch ----------------------------------------------------
extern "C" void kernel_launch(void* const* d_in, const int* in_sizes, int n_in,
                              void* d_out, int out_size) {
    const float* x          = (const float*)d_in[0];
    const float* w1         = (const float*)d_in[1];
    const float* b1         = (const float*)d_in[2];
    const float* w2         = (const float*)d_in[3];
    const float* b2         = (const float*)d_in[4];
    const float* act_range  = (const float*)d_in[5];
    const int*   cluster    = (const int*)d_in[6];
    float* out = (float*)d_out;

    fused_pcq<<<GRID_, TPB_>>>(x, w1, b1, w2, b2, act_range, cluster, out);
}

// round 9
// speedup vs baseline: 1.1775x; 1.1775x over previous
#include <cuda_runtime.h>
#include <math_constants.h>

#define B_    64
#define C_    256
#define HW_   4096          // 64*64 floats per plane = 1024 float4
#define NPLANE (B_*C_)      // 16384
#define NCL   8

__device__ float g_sum[NPLANE];
__device__ float g_min[NPLANE];
__device__ float g_max[NPLANE];
__device__ float g_scale[NPLANE];
__device__ float g_smin[B_];
__device__ float g_smax[B_];
__device__ float g_ss[B_];
__device__ float g_zz[B_];
__device__ float g_inv[B_];

// ---------------- kernel 1: per-plane sum/min/max, warp-per-plane -----------
// 2048 blocks x 256 threads; each warp owns one plane (1024 float4).
// Paired accumulators + unroll -> 8 LDG.128 batched per lane.
__global__ __launch_bounds__(256) void k1_reduce(const float* __restrict__ x) {
    const int warp  = threadIdx.x >> 5;
    const int lane  = threadIdx.x & 31;
    const int plane = blockIdx.x * 8 + warp;

    const float4* xp = reinterpret_cast<const float4*>(x + (size_t)plane * HW_);

    float s0 = 0.f, s1 = 0.f;
    float mn0 = CUDART_INF_F, mn1 = CUDART_INF_F;
    float mx0 = -CUDART_INF_F, mx1 = -CUDART_INF_F;
#pragma unroll 4
    for (int i = 0; i < 32; i += 2) {        // 32 f4/lane total
        float4 a = xp[lane + 32 * i];
        float4 b = xp[lane + 32 * (i + 1)];
        s0 += (a.x + a.y) + (a.z + a.w);
        mn0 = fminf(mn0, fminf(fminf(a.x, a.y), fminf(a.z, a.w)));
        mx0 = fmaxf(mx0, fmaxf(fmaxf(a.x, a.y), fmaxf(a.z, a.w)));
        s1 += (b.x + b.y) + (b.z + b.w);
        mn1 = fminf(mn1, fminf(fminf(b.x, b.y), fminf(b.z, b.w)));
        mx1 = fmaxf(mx1, fmaxf(fmaxf(b.x, b.y), fmaxf(b.z, b.w)));
    }
    float s  = s0 + s1;
    float mn = fminf(mn0, mn1);
    float mx = fmaxf(mx0, mx1);
#pragma unroll
    for (int o = 16; o; o >>= 1) {
        s  += __shfl_xor_sync(0xffffffffu, s, o);
        mn  = fminf(mn, __shfl_xor_sync(0xffffffffu, mn, o));
        mx  = fmaxf(mx, __shfl_xor_sync(0xffffffffu, mx, o));
    }
    if (lane == 0) {
        g_sum[plane] = s;
        g_min[plane] = mn;
        g_max[plane] = mx;
    }
}

// ---------------- kernel 2: SE MLP + per-sample min/max ---------------------
// Layer 1: warp w computes outputs o = w*8..w*8+7 with COALESCED w1 reads.
// Layer 2: per-thread float4 reads of its w2 row.
__global__ __launch_bounds__(256) void k2_se(const float* __restrict__ w1,
                                             const float* __restrict__ b1,
                                             const float* __restrict__ w2,
                                             const float* __restrict__ b2) {
    const int b = blockIdx.x;
    const int t = threadIdx.x;
    const int lane = t & 31, warp = t >> 5;
    __shared__ float pooled[C_];
    __shared__ float hbuf[64];

    pooled[t] = g_sum[b * C_ + t] * (1.0f / 4096.0f);
    __syncthreads();

    // layer 1: 8 warps x 8 outputs
#pragma unroll
    for (int k = 0; k < 8; ++k) {
        const int o = warp * 8 + k;
        const float* row = w1 + o * C_;
        float acc = 0.f;
#pragma unroll
        for (int j = 0; j < 8; ++j)
            acc = fmaf(row[lane + 32 * j], pooled[lane + 32 * j], acc);
#pragma unroll
        for (int sh = 16; sh; sh >>= 1)
            acc += __shfl_xor_sync(0xffffffffu, acc, sh);
        if (lane == 0) hbuf[o] = fmaxf(acc + b1[o], 0.0f);
    }
    __syncthreads();

    // layer 2: v[t] = b2[t] + sum_s hbuf[s] * w2[t*64+s], float4 row loads
    float v = b2[t];
    const float4* w2r = reinterpret_cast<const float4*>(w2 + t * 64);
#pragma unroll
    for (int j = 0; j < 16; ++j) {
        float4 wv = w2r[j];
        v = fmaf(hbuf[4 * j + 0], wv.x, v);
        v = fmaf(hbuf[4 * j + 1], wv.y, v);
        v = fmaf(hbuf[4 * j + 2], wv.z, v);
        v = fmaf(hbuf[4 * j + 3], wv.w, v);
    }
    float sc = fminf(fmaxf(v * (1.0f / 6.0f) + 0.5f, 0.0f), 1.0f);
    g_scale[b * C_ + t] = sc;

    float pmn = sc * g_min[b * C_ + t];   // scale >= 0: min(scale*x)=scale*min(x)
    float pmx = sc * g_max[b * C_ + t];
#pragma unroll
    for (int o = 16; o; o >>= 1) {
        pmn = fminf(pmn, __shfl_xor_sync(0xffffffffu, pmn, o));
        pmx = fmaxf(pmx, __shfl_xor_sync(0xffffffffu, pmx, o));
    }
    __shared__ float sh_mn[8], sh_mx[8];
    if (lane == 0) { sh_mn[warp] = pmn; sh_mx[warp] = pmx; }
    __syncthreads();
    if (t == 0) {
        float tmn = CUDART_INF_F, tmx = -CUDART_INF_F;
#pragma unroll
        for (int w = 0; w < 8; ++w) {
            tmn = fminf(tmn, sh_mn[w]);
            tmx = fmaxf(tmx, sh_mx[w]);
        }
        g_smin[b] = tmn;
        g_smax[b] = tmx;
    }
}

// ---------------- kernel 3: cluster EMA ranges + per-sample (s,z) -----------
__global__ __launch_bounds__(64) void k3_ranges(const float* __restrict__ act_range,
                                                const int* __restrict__ cluster) {
    __shared__ float s_s[NCL], s_z[NCL];
    const int t = threadIdx.x;
    if (t < NCL) {
        float cmin = CUDART_INF_F, cmax = -CUDART_INF_F;
        for (int b = 0; b < B_; ++b) {
            if (cluster[b] == t) {
                cmin = fminf(cmin, g_smin[b]);
                cmax = fmaxf(cmax, g_smax[b]);
            }
        }
        const float SMOOTH = 0.995f, ONE_M = 0.005f;
        float nmin = act_range[2 * t]     * SMOOTH + cmin * ONE_M;
        float nmax = act_range[2 * t + 1] * SMOOTH + cmax * ONE_M;
        float s = (nmax - nmin) * (1.0f / 255.0f);
        s_s[t] = s;
        s_z[t] = -rintf(nmin / s);
    }
    __syncthreads();
    if (t < B_) {
        int k = cluster[t];
        g_ss[t]  = s_s[k];
        g_zz[t]  = s_z[k];
        g_inv[t] = 1.0f / s_s[k];
    }
}

// ---------------- kernel 4: streaming scale + fake-quant (R1 known-good) ----
__global__ __launch_bounds__(256) void k4_quant(const float* __restrict__ x,
                                                float* __restrict__ out) {
    const int plane = blockIdx.x;
    const int b = plane >> 8;
    const float sc  = g_scale[plane];
    const float ssv = g_ss[b];
    const float zzv = g_zz[b];
    const float inv = g_inv[b];

    const float4* xp = reinterpret_cast<const float4*>(x   + (size_t)plane * HW_);
    float4*       op = reinterpret_cast<float4*>      (out + (size_t)plane * HW_);

#pragma unroll
    for (int i = 0; i < 4; ++i) {
        float4 v = xp[threadIdx.x + 256 * i];
        float4 r;
        {
            float o = sc * v.x;
            float q = fminf(fmaxf(rintf(fmaf(o, inv, zzv)), 0.0f), 255.0f);
            r.x = (q - zzv) * ssv;
        }
        {
            float o = sc * v.y;
            float q = fminf(fmaxf(rintf(fmaf(o, inv, zzv)), 0.0f), 255.0f);
            r.y = (q - zzv) * ssv;
        }
        {
            float o = sc * v.z;
            float q = fminf(fmaxf(rintf(fmaf(o, inv, zzv)), 0.0f), 255.0f);
            r.z = (q - zzv) * ssv;
        }
        {
            float o = sc * v.w;
            float q = fminf(fmaxf(rintf(fmaf(o, inv, zzv)), 0.0f), 255.0f);
            r.w = (q - zzv) * ssv;
        }
        op[threadIdx.x + 256 * i] = r;
    }
}

// ---------------- launch ----------------------------------------------------
extern "C" void kernel_launch(void* const* d_in, const int* in_sizes, int n_in,
                              void* d_out, int out_size) {
    const float* x          = (const float*)d_in[0];
    const float* w1         = (const float*)d_in[1];
    const float* b1         = (const float*)d_in[2];
    const float* w2         = (const float*)d_in[3];
    const float* b2         = (const float*)d_in[4];
    const float* act_range  = (const float*)d_in[5];
    const int*   cluster    = (const int*)d_in[6];
    float* out = (float*)d_out;

    k1_reduce<<<NPLANE / 8, 256>>>(x);
    k2_se<<<B_, 256>>>(w1, b1, w2, b2);
    k3_ranges<<<1, 64>>>(act_range, cluster);
    k4_quant<<<NPLANE, 256>>>(x, out);
}